// round 8
// baseline (speedup 1.0000x reference)
#include <cuda_runtime.h>

#define B    16
#define T    4096
#define DIN  64
#define DOUT 64
#define H    128
#define NC   64          // number of chunks
#define CHUNK 64         // T / NC

#define XN   (B * T * DIN)           // 4194304 elements per x buffer
#define WHN  (H * H)                 // 16384
#define WIN  (H * DIN)               // 8192
#define OUTP (B * T * DOUT)          // 4194304 output positions (complex)

// ---------------- small scratch (~2.6 MB total) ----------------
__device__ float2 g_M[H * H];        // M[k][j] = i * Wh[j][k]
__device__ float2 g_P0[H * H];       // ping-pong for repeated squaring
__device__ float2 g_P1[H * H];       // ends as M^CHUNK
__device__ float2 g_WI2[DIN * H];    // Wi packed (re,im), d-major
__device__ float2 g_WO2[H * DOUT];   // Wo packed (re,im), k-major
__device__ float2 g_L[NC * B * H];   // chunk-local end states
__device__ float2 g_S[NC * B * H];   // scanned chunk-end states

__device__ __forceinline__ int iclamp(int i, int bound) {
    return (i < bound) ? ((i >= 0) ? i : 0) : (bound - 1);
}

// ---------------- K0: build M, packed Wi, packed Wo (all reads clamped) ----------------
__global__ void prep_kernel(const float* __restrict__ Wir, const float* __restrict__ Wii, int bWi,
                            const float* __restrict__ Whr, const float* __restrict__ Whi, int bWh,
                            const float* __restrict__ Wor, const float* __restrict__ Woi, int bWo) {
    int idx = blockIdx.x * blockDim.x + threadIdx.x;
    if (idx < H * H) {                       // M[k*H + j] = i * Wh[j][k]
        int k = idx / H, j = idx - k * H;
        int s = iclamp(j * H + k, bWh);
        g_M[idx] = make_float2(-Whi[s], Whr[s]);
    }
    if (idx < DIN * H) {                     // WI2[d*H + j] = (Wir[j][d], Wii[j][d])
        int d = idx / H, j = idx - d * H;
        int s = iclamp(j * DIN + d, bWi);
        g_WI2[idx] = make_float2(Wir[s], Wii[s]);
    }
    if (idx < H * DOUT) {                    // WO2[k*DOUT + o] = (Wor[o][k], Woi[o][k])
        int k = idx / DOUT, o = idx - k * DOUT;
        int s = iclamp(o * H + k, bWo);
        g_WO2[idx] = make_float2(Wor[s], Woi[s]);
    }
}

// ---------------- K1: complex matrix squaring (for M^CHUNK) ----------------
__global__ void matsq_kernel(int mode) {
    const float2* A = (mode == 0) ? g_M : ((mode & 1) ? g_P0 : g_P1);
    float2* Cd = (mode & 1) ? g_P1 : g_P0;
    __shared__ float2 arow[H];               // 1 KB
    int k = blockIdx.x, j = threadIdx.x;
    arow[j] = A[k * H + j];
    __syncthreads();
    float re = 0.f, im = 0.f;
#pragma unroll 4
    for (int p = 0; p < H; p++) {
        float2 a = arow[p];
        float2 bb = A[p * H + j];
        re = fmaf(a.x, bb.x, re);
        re = fmaf(-a.y, bb.y, re);
        im = fmaf(a.x, bb.y, im);
        im = fmaf(a.y, bb.x, im);
    }
    Cd[k * H + j] = make_float2(re, im);
}

// ---------------- K2: phase A — local recurrence per chunk, store end state ----------------
// grid 128 = (chunk, batch-half), 256 threads = (j, g). Static smem 12 KB.
__global__ void phaseA_kernel(const float* __restrict__ xr, const float* __restrict__ xi,
                              int xbound) {
    __shared__ float2 shH[8 * H];            // 8 KB
    __shared__ float2 shX[8 * DIN];          // 4 KB
    int tid = threadIdx.x;
    int j = tid & (H - 1);
    int g = tid >> 7;
    int c = blockIdx.x >> 1;
    int bbase = (blockIdx.x & 1) * 8;

    for (int i = tid; i < 8 * H; i += 256) shH[i] = make_float2(0.f, 0.f);
    __syncthreads();

    int t0 = c * CHUNK;
    float aRe[4], aIm[4];
    for (int js = 0; js < CHUNK; js++) {
        int t = t0 + js;
        for (int i = tid; i < 8 * DIN; i += 256) {
            int row = i >> 6, d = i & 63;
            int src = iclamp(((bbase + row) * T + t) * DIN + d, xbound);
            shX[i] = make_float2(xr[src], xi[src]);
        }
        __syncthreads();
#pragma unroll
        for (int m = 0; m < 4; m++) { aRe[m] = 0.f; aIm[m] = 0.f; }
#pragma unroll 4
        for (int d = 0; d < DIN; d++) {
            float2 w = g_WI2[d * H + j];
#pragma unroll
            for (int m = 0; m < 4; m++) {
                float2 hv = shX[(g * 4 + m) * DIN + d];
                aRe[m] = fmaf(hv.x, w.x, aRe[m]);
                aRe[m] = fmaf(-hv.y, w.y, aRe[m]);
                aIm[m] = fmaf(hv.x, w.y, aIm[m]);
                aIm[m] = fmaf(hv.y, w.x, aIm[m]);
            }
        }
#pragma unroll 2
        for (int k = 0; k < H; k++) {
            float2 w = g_M[k * H + j];
#pragma unroll
            for (int m = 0; m < 4; m++) {
                float2 hv = shH[(g * 4 + m) * H + k];
                aRe[m] = fmaf(hv.x, w.x, aRe[m]);
                aRe[m] = fmaf(-hv.y, w.y, aRe[m]);
                aIm[m] = fmaf(hv.x, w.y, aIm[m]);
                aIm[m] = fmaf(hv.y, w.x, aIm[m]);
            }
        }
        __syncthreads();
#pragma unroll
        for (int m = 0; m < 4; m++)
            shH[(g * 4 + m) * H + j] = make_float2(aRe[m], aIm[m]);
        __syncthreads();
    }
#pragma unroll
    for (int m = 0; m < 4; m++)
        g_L[(c * B + bbase + g * 4 + m) * H + j] = make_float2(aRe[m], aIm[m]);
}

// ---------------- K3: phase 2 — boundary scan S_c = L_c + S_{c-1} * M^64 ----------------
__global__ void phase2_kernel() {
    __shared__ float2 shS[H];                // 1 KB
    int h = threadIdx.x;       // 128 threads
    int b = blockIdx.x;        // 16 blocks
    float2 s = g_L[b * H + h];
    g_S[b * H + h] = s;
    shS[h] = s;
    __syncthreads();
    for (int c = 1; c < NC; c++) {
        float re = 0.f, im = 0.f;
#pragma unroll 4
        for (int k = 0; k < H; k++) {
            float2 w = g_P1[k * H + h];
            float2 hv = shS[k];
            re = fmaf(hv.x, w.x, re);
            re = fmaf(-hv.y, w.y, re);
            im = fmaf(hv.x, w.y, im);
            im = fmaf(hv.y, w.x, im);
        }
        __syncthreads();
        float2 l = g_L[(c * B + b) * H + h];
        s = make_float2(l.x + re, l.y + im);
        g_S[(c * B + b) * H + h] = s;
        shS[h] = s;
        __syncthreads();
    }
}

// ---------------- K4: phase B — exact-init replay + fused output projection ----------------
// Output layout adaptive: interleave==1 -> (re,im) pairs; 0 -> real part only.
// EVERY float store individually clamped by fcap (out_size in float elements).
__global__ void phaseB_kernel(const float* __restrict__ xr, const float* __restrict__ xi,
                              int xbound, float* __restrict__ outf, int fcap, int interleave) {
    __shared__ float2 shH[8 * H];            // 8 KB
    __shared__ float2 shX[8 * DIN];          // 4 KB
    __shared__ float2 shP[8 * H];            // 8 KB partials
    int tid = threadIdx.x;
    int j = tid & (H - 1);
    int g = tid >> 7;
    int c = blockIdx.x >> 1;
    int bbase = (blockIdx.x & 1) * 8;
    int o = j & (DOUT - 1);
    int half = j >> 6;

    for (int i = tid; i < 8 * H; i += 256) {
        int row = i >> 7, k = i & (H - 1);
        shH[i] = (c == 0) ? make_float2(0.f, 0.f)
                          : g_S[((c - 1) * B + bbase + row) * H + k];
    }
    __syncthreads();

    int t0 = c * CHUNK;
    for (int js = 0; js < CHUNK; js++) {
        int t = t0 + js;
        for (int i = tid; i < 8 * DIN; i += 256) {
            int row = i >> 6, d = i & 63;
            int src = iclamp(((bbase + row) * T + t) * DIN + d, xbound);
            shX[i] = make_float2(xr[src], xi[src]);
        }
        __syncthreads();
        float aRe[4] = {0.f, 0.f, 0.f, 0.f}, aIm[4] = {0.f, 0.f, 0.f, 0.f};
#pragma unroll 4
        for (int d = 0; d < DIN; d++) {
            float2 w = g_WI2[d * H + j];
#pragma unroll
            for (int m = 0; m < 4; m++) {
                float2 hv = shX[(g * 4 + m) * DIN + d];
                aRe[m] = fmaf(hv.x, w.x, aRe[m]);
                aRe[m] = fmaf(-hv.y, w.y, aRe[m]);
                aIm[m] = fmaf(hv.x, w.y, aIm[m]);
                aIm[m] = fmaf(hv.y, w.x, aIm[m]);
            }
        }
#pragma unroll 2
        for (int k = 0; k < H; k++) {
            float2 w = g_M[k * H + j];
#pragma unroll
            for (int m = 0; m < 4; m++) {
                float2 hv = shH[(g * 4 + m) * H + k];
                aRe[m] = fmaf(hv.x, w.x, aRe[m]);
                aRe[m] = fmaf(-hv.y, w.y, aRe[m]);
                aIm[m] = fmaf(hv.x, w.y, aIm[m]);
                aIm[m] = fmaf(hv.y, w.x, aIm[m]);
            }
        }
        __syncthreads();
#pragma unroll
        for (int m = 0; m < 4; m++)
            shH[(g * 4 + m) * H + j] = make_float2(aRe[m], aIm[m]);
        __syncthreads();
        // fused output projection partials over this thread's 64-k half
        float pRe[4] = {0.f, 0.f, 0.f, 0.f}, pIm[4] = {0.f, 0.f, 0.f, 0.f};
#pragma unroll 2
        for (int kk = 0; kk < 64; kk++) {
            int k = half * 64 + kk;
            float2 w = g_WO2[k * DOUT + o];
#pragma unroll
            for (int m = 0; m < 4; m++) {
                float2 hv = shH[(g * 4 + m) * H + k];
                pRe[m] = fmaf(hv.x, w.x, pRe[m]);
                pRe[m] = fmaf(-hv.y, w.y, pRe[m]);
                pIm[m] = fmaf(hv.x, w.y, pIm[m]);
                pIm[m] = fmaf(hv.y, w.x, pIm[m]);
            }
        }
#pragma unroll
        for (int m = 0; m < 4; m++)
            shP[(g * 4 + m) * H + half * 64 + o] = make_float2(pRe[m], pIm[m]);
        __syncthreads();
#pragma unroll
        for (int u = 0; u < 2; u++) {
            int r = g * 4 + half * 2 + u;
            float2 p0 = shP[r * H + o];
            float2 p1 = shP[r * H + 64 + o];
            float re = p0.x + p1.x;
            float im = p0.y + p1.y;
            int oi = ((bbase + r) * T + t) * DOUT + o;   // 0 .. OUTP-1
            if (interleave) {
                int f0 = 2 * oi;
                if (f0 + 1 < fcap) { outf[f0] = re; outf[f0 + 1] = im; }
            } else {
                if (oi < fcap) outf[oi] = re;            // real part only
            }
        }
        __syncthreads();
    }
}

// ---------------- launch ----------------
static inline int ebound(int reported, int expected) {
    // strictly conservative element bound: never exceed either
    if (reported >= 1 && reported < expected) return reported;
    return expected;
}
static inline int gidx(int i, int n_in) { return (i >= 0 && i < n_in) ? i : 0; }

extern "C" void kernel_launch(void* const* d_in, const int* in_sizes, int n_in,
                              void* d_out, int out_size) {
    // size-classified mapping (robust to insertion vs sorted metadata order)
    int ix[2] = {0, 1}, iwh[2] = {4, 5}, iw8[4] = {2, 3, 6, 7};
    int nx = 0, nwh = 0, n8 = 0;
    for (int i = 0; i < n_in; i++) {
        int s = in_sizes[i];
        if (s == XN)        { if (nx  < 2) ix[nx++]  = i; }
        else if (s == WHN)  { if (nwh < 2) iwh[nwh++] = i; }
        else if (s == WIN)  { if (n8  < 4) iw8[n8++]  = i; }
    }
    const float* xr  = (const float*)d_in[gidx(ix[0],  n_in)];
    const float* xi  = (const float*)d_in[gidx(ix[1],  n_in)];
    const float* Wir = (const float*)d_in[gidx(iw8[0], n_in)];
    const float* Wii = (const float*)d_in[gidx(iw8[1], n_in)];
    const float* Wor = (const float*)d_in[gidx(iw8[2], n_in)];
    const float* Woi = (const float*)d_in[gidx(iw8[3], n_in)];
    const float* Whr = (const float*)d_in[gidx(iwh[0], n_in)];
    const float* Whi = (const float*)d_in[gidx(iwh[1], n_in)];

    int bx  = ebound(in_sizes[gidx(ix[0],  n_in)], XN);
    int b2  = ebound(in_sizes[gidx(ix[1],  n_in)], XN);   if (b2 < bx)  bx  = b2;
    int bwi = ebound(in_sizes[gidx(iw8[0], n_in)], WIN);
    b2      = ebound(in_sizes[gidx(iw8[1], n_in)], WIN);  if (b2 < bwi) bwi = b2;
    int bwo = ebound(in_sizes[gidx(iw8[2], n_in)], WIN);
    b2      = ebound(in_sizes[gidx(iw8[3], n_in)], WIN);  if (b2 < bwo) bwo = b2;
    int bwh = ebound(in_sizes[gidx(iwh[0], n_in)], WHN);
    b2      = ebound(in_sizes[gidx(iwh[1], n_in)], WHN);  if (b2 < bwh) bwh = b2;

    // out_size = number of float32 elements in d_out (harness: "out_size elements
    // of the __output__ dtype"). NEVER write >= out_size floats.
    int fcap = out_size;
    if (fcap < 1) fcap = 1;
    if (fcap > 2 * OUTP) fcap = 2 * OUTP;
    int interleave = (fcap > OUTP) ? 1 : 0;   // 2*OUTP floats -> (re,im); OUTP -> real only

    prep_kernel<<<(H * H + 255) / 256, 256>>>(Wir, Wii, bwi,
                                              Whr, Whi, bwh,
                                              Wor, Woi, bwo);
    for (int mode = 0; mode < 6; mode++)       // M^2 .. M^64 -> g_P1
        matsq_kernel<<<H, H>>>(mode);
    phaseA_kernel<<<NC * 2, 256>>>(xr, xi, bx);
    phase2_kernel<<<B, H>>>();
    phaseB_kernel<<<NC * 2, 256>>>(xr, xi, bx, (float*)d_out, fcap, interleave);
}

// round 9
// speedup vs baseline: 1.3317x; 1.3317x over previous
#include <cuda_runtime.h>

#define B    16
#define T    4096
#define DIN  64
#define DOUT 64
#define H    128
#define NC   64          // number of chunks
#define CHUNK 64         // T / NC

#define XN   (B * T * DIN)           // 4194304 elements per x buffer
#define WHN  (H * H)                 // 16384
#define WIN  (H * DIN)               // 8192
#define OUTP (B * T * DOUT)          // 4194304 output positions (complex)

// ---------------- small scratch (~2.6 MB total) ----------------
__device__ float2 g_M[H * H];        // M[k][j] = i * Wh[j][k]
__device__ float2 g_P0[H * H];       // ping-pong for repeated squaring
__device__ float2 g_P1[H * H];       // ends as M^CHUNK
__device__ float2 g_WI2[DIN * H];    // Wi packed (re,im), d-major
__device__ float2 g_WO2[H * DOUT];   // Wo packed (re,im), k-major
__device__ float2 g_L[NC * B * H];   // chunk-local end states
__device__ float2 g_S[NC * B * H];   // scanned chunk-end states

__device__ __forceinline__ int iclamp(int i, int bound) {
    return (i < bound) ? ((i >= 0) ? i : 0) : (bound - 1);
}

// ---------------- packed f32x2 helpers ----------------
__device__ __forceinline__ unsigned long long ffma2(unsigned long long a,
                                                    unsigned long long b,
                                                    unsigned long long c) {
    unsigned long long d;
    asm("fma.rn.f32x2 %0, %1, %2, %3;" : "=l"(d) : "l"(a), "l"(b), "l"(c));
    return d;
}
__device__ __forceinline__ unsigned long long dup2(float x) {
    unsigned int u = __float_as_uint(x);
    return ((unsigned long long)u << 32) | (unsigned long long)u;
}
__device__ __forceinline__ float lo2(unsigned long long v) {
    return __uint_as_float((unsigned int)v);
}
__device__ __forceinline__ float hi2(unsigned long long v) {
    return __uint_as_float((unsigned int)(v >> 32));
}

// ---------------- K0: build M, packed Wi, packed Wo (all reads clamped) ----------------
__global__ void prep_kernel(const float* __restrict__ Wir, const float* __restrict__ Wii, int bWi,
                            const float* __restrict__ Whr, const float* __restrict__ Whi, int bWh,
                            const float* __restrict__ Wor, const float* __restrict__ Woi, int bWo) {
    int idx = blockIdx.x * blockDim.x + threadIdx.x;
    if (idx < H * H) {                       // M[k*H + j] = i * Wh[j][k]
        int k = idx / H, j = idx - k * H;
        int s = iclamp(j * H + k, bWh);
        g_M[idx] = make_float2(-Whi[s], Whr[s]);
    }
    if (idx < DIN * H) {                     // WI2[d*H + j] = (Wir[j][d], Wii[j][d])
        int d = idx / H, j = idx - d * H;
        int s = iclamp(j * DIN + d, bWi);
        g_WI2[idx] = make_float2(Wir[s], Wii[s]);
    }
    if (idx < H * DOUT) {                    // WO2[k*DOUT + o] = (Wor[o][k], Woi[o][k])
        int k = idx / DOUT, o = idx - k * DOUT;
        int s = iclamp(o * H + k, bWo);
        g_WO2[idx] = make_float2(Wor[s], Woi[s]);
    }
}

// ---------------- K1: complex matrix squaring (for M^CHUNK) ----------------
__global__ void matsq_kernel(int mode) {
    const float2* A = (mode == 0) ? g_M : ((mode & 1) ? g_P0 : g_P1);
    float2* Cd = (mode & 1) ? g_P1 : g_P0;
    __shared__ float2 arow[H];               // 1 KB
    int k = blockIdx.x, j = threadIdx.x;
    arow[j] = A[k * H + j];
    __syncthreads();
    float re = 0.f, im = 0.f;
#pragma unroll 4
    for (int p = 0; p < H; p++) {
        float2 a = arow[p];
        float2 bb = A[p * H + j];
        re = fmaf(a.x, bb.x, re);
        re = fmaf(-a.y, bb.y, re);
        im = fmaf(a.x, bb.y, im);
        im = fmaf(a.y, bb.x, im);
    }
    Cd[k * H + j] = make_float2(re, im);
}

// ---------------- K2: phase A — local recurrence per chunk (f32x2 packed) ----------------
// grid 128 = (chunk, batch-half), 256 threads = (j, g). Static smem 24 KB.
__global__ void phaseA_kernel(const float* __restrict__ xr, const float* __restrict__ xi,
                              int xbound) {
    __shared__ ulonglong2 shH[8 * H];        // 16 KB  (dup(re), dup(im))
    __shared__ ulonglong2 shX[8 * DIN];      // 8 KB
    int tid = threadIdx.x;
    int j = tid & (H - 1);
    int g = tid >> 7;
    int c = blockIdx.x >> 1;
    int bbase = (blockIdx.x & 1) * 8;

    for (int i = tid; i < 8 * H; i += 256) shH[i] = make_ulonglong2(0ULL, 0ULL);

    int t0 = c * CHUNK;
    // prefetch step 0's x (each thread owns 2 of the 512 staged elements)
    float2 pre[2];
#pragma unroll
    for (int u = 0; u < 2; u++) {
        int i = tid + 256 * u;
        int row = i >> 6, d = i & 63;
        int src = iclamp(((bbase + row) * T + t0) * DIN + d, xbound);
        pre[u] = make_float2(xr[src], xi[src]);
    }
    __syncthreads();

    float rRe[4], rIm[4];
    for (int js = 0; js < CHUNK; js++) {
        // stage prefetched x
#pragma unroll
        for (int u = 0; u < 2; u++)
            shX[tid + 256 * u] = make_ulonglong2(dup2(pre[u].x), dup2(pre[u].y));
        __syncthreads();
        // prefetch next step (LDG in flight during compute)
        if (js + 1 < CHUNK) {
            int t1 = t0 + js + 1;
#pragma unroll
            for (int u = 0; u < 2; u++) {
                int i = tid + 256 * u;
                int row = i >> 6, d = i & 63;
                int src = iclamp(((bbase + row) * T + t1) * DIN + d, xbound);
                pre[u] = make_float2(xr[src], xi[src]);
            }
        }
        unsigned long long accA[4] = {0, 0, 0, 0}, accB[4] = {0, 0, 0, 0};
#pragma unroll 4
        for (int d = 0; d < DIN; d++) {
            unsigned long long w = *(const unsigned long long*)(g_WI2 + d * H + j);
#pragma unroll
            for (int m = 0; m < 4; m++) {
                ulonglong2 hv = shX[(g * 4 + m) * DIN + d];
                accA[m] = ffma2(hv.x, w, accA[m]);
                accB[m] = ffma2(hv.y, w, accB[m]);
            }
        }
#pragma unroll 4
        for (int k = 0; k < H; k++) {
            unsigned long long w = *(const unsigned long long*)(g_M + k * H + j);
#pragma unroll
            for (int m = 0; m < 4; m++) {
                ulonglong2 hv = shH[(g * 4 + m) * H + k];
                accA[m] = ffma2(hv.x, w, accA[m]);
                accB[m] = ffma2(hv.y, w, accB[m]);
            }
        }
        __syncthreads();
#pragma unroll
        for (int m = 0; m < 4; m++) {
            rRe[m] = lo2(accA[m]) - hi2(accB[m]);
            rIm[m] = hi2(accA[m]) + lo2(accB[m]);
            shH[(g * 4 + m) * H + j] = make_ulonglong2(dup2(rRe[m]), dup2(rIm[m]));
        }
        __syncthreads();
    }
#pragma unroll
    for (int m = 0; m < 4; m++)
        g_L[(c * B + bbase + g * 4 + m) * H + j] = make_float2(rRe[m], rIm[m]);
}

// ---------------- K3: phase 2 — boundary scan S_c = L_c + S_{c-1} * M^64 ----------------
__global__ void phase2_kernel() {
    __shared__ float2 shS[H];                // 1 KB
    int h = threadIdx.x;       // 128 threads
    int b = blockIdx.x;        // 16 blocks
    float2 s = g_L[b * H + h];
    g_S[b * H + h] = s;
    shS[h] = s;
    __syncthreads();
    for (int c = 1; c < NC; c++) {
        float re = 0.f, im = 0.f;
#pragma unroll 4
        for (int k = 0; k < H; k++) {
            float2 w = g_P1[k * H + h];
            float2 hv = shS[k];
            re = fmaf(hv.x, w.x, re);
            re = fmaf(-hv.y, w.y, re);
            im = fmaf(hv.x, w.y, im);
            im = fmaf(hv.y, w.x, im);
        }
        __syncthreads();
        float2 l = g_L[(c * B + b) * H + h];
        s = make_float2(l.x + re, l.y + im);
        g_S[(c * B + b) * H + h] = s;
        shS[h] = s;
        __syncthreads();
    }
}

// ---------------- K4: phase B — exact-init replay + fused output projection (f32x2) ----------------
// Output layout adaptive: interleave==1 -> (re,im) pairs; 0 -> real part only.
// EVERY float store individually clamped by fcap (out_size in float elements).
__global__ void phaseB_kernel(const float* __restrict__ xr, const float* __restrict__ xi,
                              int xbound, float* __restrict__ outf, int fcap, int interleave) {
    __shared__ ulonglong2 shH[8 * H];        // 16 KB
    __shared__ ulonglong2 shX[8 * DIN];      // 8 KB
    __shared__ float2 shP[8 * H];            // 8 KB partials
    int tid = threadIdx.x;
    int j = tid & (H - 1);
    int g = tid >> 7;
    int c = blockIdx.x >> 1;
    int bbase = (blockIdx.x & 1) * 8;
    int o = j & (DOUT - 1);
    int half = j >> 6;

    for (int i = tid; i < 8 * H; i += 256) {
        int row = i >> 7, k = i & (H - 1);
        float2 s = (c == 0) ? make_float2(0.f, 0.f)
                            : g_S[((c - 1) * B + bbase + row) * H + k];
        shH[i] = make_ulonglong2(dup2(s.x), dup2(s.y));
    }

    int t0 = c * CHUNK;
    float2 pre[2];
#pragma unroll
    for (int u = 0; u < 2; u++) {
        int i = tid + 256 * u;
        int row = i >> 6, d = i & 63;
        int src = iclamp(((bbase + row) * T + t0) * DIN + d, xbound);
        pre[u] = make_float2(xr[src], xi[src]);
    }
    __syncthreads();

    for (int js = 0; js < CHUNK; js++) {
        int t = t0 + js;
#pragma unroll
        for (int u = 0; u < 2; u++)
            shX[tid + 256 * u] = make_ulonglong2(dup2(pre[u].x), dup2(pre[u].y));
        __syncthreads();
        if (js + 1 < CHUNK) {
            int t1 = t + 1;
#pragma unroll
            for (int u = 0; u < 2; u++) {
                int i = tid + 256 * u;
                int row = i >> 6, d = i & 63;
                int src = iclamp(((bbase + row) * T + t1) * DIN + d, xbound);
                pre[u] = make_float2(xr[src], xi[src]);
            }
        }
        unsigned long long accA[4] = {0, 0, 0, 0}, accB[4] = {0, 0, 0, 0};
#pragma unroll 4
        for (int d = 0; d < DIN; d++) {
            unsigned long long w = *(const unsigned long long*)(g_WI2 + d * H + j);
#pragma unroll
            for (int m = 0; m < 4; m++) {
                ulonglong2 hv = shX[(g * 4 + m) * DIN + d];
                accA[m] = ffma2(hv.x, w, accA[m]);
                accB[m] = ffma2(hv.y, w, accB[m]);
            }
        }
#pragma unroll 4
        for (int k = 0; k < H; k++) {
            unsigned long long w = *(const unsigned long long*)(g_M + k * H + j);
#pragma unroll
            for (int m = 0; m < 4; m++) {
                ulonglong2 hv = shH[(g * 4 + m) * H + k];
                accA[m] = ffma2(hv.x, w, accA[m]);
                accB[m] = ffma2(hv.y, w, accB[m]);
            }
        }
        __syncthreads();
#pragma unroll
        for (int m = 0; m < 4; m++) {
            float re = lo2(accA[m]) - hi2(accB[m]);
            float im = hi2(accA[m]) + lo2(accB[m]);
            shH[(g * 4 + m) * H + j] = make_ulonglong2(dup2(re), dup2(im));
        }
        __syncthreads();
        // fused output projection partials over this thread's 64-k half (packed)
        unsigned long long pA[4] = {0, 0, 0, 0}, pB[4] = {0, 0, 0, 0};
#pragma unroll 4
        for (int kk = 0; kk < 64; kk++) {
            int k = half * 64 + kk;
            unsigned long long w = *(const unsigned long long*)(g_WO2 + k * DOUT + o);
#pragma unroll
            for (int m = 0; m < 4; m++) {
                ulonglong2 hv = shH[(g * 4 + m) * H + k];
                pA[m] = ffma2(hv.x, w, pA[m]);
                pB[m] = ffma2(hv.y, w, pB[m]);
            }
        }
#pragma unroll
        for (int m = 0; m < 4; m++)
            shP[(g * 4 + m) * H + half * 64 + o] =
                make_float2(lo2(pA[m]) - hi2(pB[m]), hi2(pA[m]) + lo2(pB[m]));
        __syncthreads();
#pragma unroll
        for (int u = 0; u < 2; u++) {
            int r = g * 4 + half * 2 + u;
            float2 p0 = shP[r * H + o];
            float2 p1 = shP[r * H + 64 + o];
            float re = p0.x + p1.x;
            float im = p0.y + p1.y;
            int oi = ((bbase + r) * T + t) * DOUT + o;   // 0 .. OUTP-1
            if (interleave) {
                int f0 = 2 * oi;
                if (f0 + 1 < fcap) { outf[f0] = re; outf[f0 + 1] = im; }
            } else {
                if (oi < fcap) outf[oi] = re;            // real part only
            }
        }
        __syncthreads();
    }
}

// ---------------- launch ----------------
static inline int ebound(int reported, int expected) {
    if (reported >= 1 && reported < expected) return reported;
    return expected;
}
static inline int gidx(int i, int n_in) { return (i >= 0 && i < n_in) ? i : 0; }

extern "C" void kernel_launch(void* const* d_in, const int* in_sizes, int n_in,
                              void* d_out, int out_size) {
    int ix[2] = {0, 1}, iwh[2] = {4, 5}, iw8[4] = {2, 3, 6, 7};
    int nx = 0, nwh = 0, n8 = 0;
    for (int i = 0; i < n_in; i++) {
        int s = in_sizes[i];
        if (s == XN)        { if (nx  < 2) ix[nx++]  = i; }
        else if (s == WHN)  { if (nwh < 2) iwh[nwh++] = i; }
        else if (s == WIN)  { if (n8  < 4) iw8[n8++]  = i; }
    }
    const float* xr  = (const float*)d_in[gidx(ix[0],  n_in)];
    const float* xi  = (const float*)d_in[gidx(ix[1],  n_in)];
    const float* Wir = (const float*)d_in[gidx(iw8[0], n_in)];
    const float* Wii = (const float*)d_in[gidx(iw8[1], n_in)];
    const float* Wor = (const float*)d_in[gidx(iw8[2], n_in)];
    const float* Woi = (const float*)d_in[gidx(iw8[3], n_in)];
    const float* Whr = (const float*)d_in[gidx(iwh[0], n_in)];
    const float* Whi = (const float*)d_in[gidx(iwh[1], n_in)];

    int bx  = ebound(in_sizes[gidx(ix[0],  n_in)], XN);
    int b2  = ebound(in_sizes[gidx(ix[1],  n_in)], XN);   if (b2 < bx)  bx  = b2;
    int bwi = ebound(in_sizes[gidx(iw8[0], n_in)], WIN);
    b2      = ebound(in_sizes[gidx(iw8[1], n_in)], WIN);  if (b2 < bwi) bwi = b2;
    int bwo = ebound(in_sizes[gidx(iw8[2], n_in)], WIN);
    b2      = ebound(in_sizes[gidx(iw8[3], n_in)], WIN);  if (b2 < bwo) bwo = b2;
    int bwh = ebound(in_sizes[gidx(iwh[0], n_in)], WHN);
    b2      = ebound(in_sizes[gidx(iwh[1], n_in)], WHN);  if (b2 < bwh) bwh = b2;

    // out_size = number of float32 elements in d_out. NEVER write >= out_size floats.
    int fcap = out_size;
    if (fcap < 1) fcap = 1;
    if (fcap > 2 * OUTP) fcap = 2 * OUTP;
    int interleave = (fcap > OUTP) ? 1 : 0;   // 2*OUTP floats -> (re,im); OUTP -> real only

    prep_kernel<<<(H * H + 255) / 256, 256>>>(Wir, Wii, bwi,
                                              Whr, Whi, bwh,
                                              Wor, Woi, bwo);
    for (int mode = 0; mode < 6; mode++)       // M^2 .. M^64 -> g_P1
        matsq_kernel<<<H, H>>>(mode);
    phaseA_kernel<<<NC * 2, 256>>>(xr, xi, bx);
    phase2_kernel<<<B, H>>>();
    phaseB_kernel<<<NC * 2, 256>>>(xr, xi, bx, (float*)d_out, fcap, interleave);
}

// round 10
// speedup vs baseline: 1.9411x; 1.4576x over previous
#include <cuda_runtime.h>

#define B    16
#define T    4096
#define DIN  64
#define DOUT 64
#define H    128
#define NC   64          // number of chunks
#define CHUNK 64         // T / NC

#define XN   (B * T * DIN)           // 4194304 elements per x buffer
#define WHN  (H * H)                 // 16384
#define WIN  (H * DIN)               // 8192
#define OUTP (B * T * DOUT)          // 4194304 output positions (complex)

// ---------------- scratch ----------------
__device__ float2 g_xp[B * T * H];   // input projection, 64 MB (safe: IMA was output contract)
__device__ float2 g_M[H * H];        // M[k][j] = i * Wh[j][k]
__device__ float2 g_P0[H * H];       // ping-pong for repeated squaring
__device__ float2 g_P1[H * H];       // ends as M^CHUNK
__device__ float2 g_WI2[DIN * H];    // Wi packed (re,im), d-major
__device__ float2 g_WO2[H * DOUT];   // Wo packed (re,im), k-major
__device__ float2 g_L[NC * B * H];   // chunk-local end states
__device__ float2 g_S[NC * B * H];   // scanned chunk-end states

__device__ __forceinline__ int iclamp(int i, int bound) {
    return (i < bound) ? ((i >= 0) ? i : 0) : (bound - 1);
}

// ---------------- packed f32x2 helpers ----------------
__device__ __forceinline__ unsigned long long ffma2(unsigned long long a,
                                                    unsigned long long b,
                                                    unsigned long long c) {
    unsigned long long d;
    asm("fma.rn.f32x2 %0, %1, %2, %3;" : "=l"(d) : "l"(a), "l"(b), "l"(c));
    return d;
}
__device__ __forceinline__ unsigned long long dup2(float x) {
    unsigned int u = __float_as_uint(x);
    return ((unsigned long long)u << 32) | (unsigned long long)u;
}
__device__ __forceinline__ float lo2(unsigned long long v) {
    return __uint_as_float((unsigned int)v);
}
__device__ __forceinline__ float hi2(unsigned long long v) {
    return __uint_as_float((unsigned int)(v >> 32));
}

// ---------------- K0: build M, packed Wi, packed Wo (reads clamped) ----------------
__global__ void prep_kernel(const float* __restrict__ Wir, const float* __restrict__ Wii, int bWi,
                            const float* __restrict__ Whr, const float* __restrict__ Whi, int bWh,
                            const float* __restrict__ Wor, const float* __restrict__ Woi, int bWo) {
    int idx = blockIdx.x * blockDim.x + threadIdx.x;
    if (idx < H * H) {
        int k = idx / H, j = idx - k * H;
        int s = iclamp(j * H + k, bWh);
        g_M[idx] = make_float2(-Whi[s], Whr[s]);
    }
    if (idx < DIN * H) {
        int d = idx / H, j = idx - d * H;
        int s = iclamp(j * DIN + d, bWi);
        g_WI2[idx] = make_float2(Wir[s], Wii[s]);
    }
    if (idx < H * DOUT) {
        int k = idx / DOUT, o = idx - k * DOUT;
        int s = iclamp(o * H + k, bWo);
        g_WO2[idx] = make_float2(Wor[s], Woi[s]);
    }
}

// ---------------- K1: input projection xp = x @ Wi^T (f32x2), once ----------------
#define R1 16
__global__ void proj_in_kernel(const float* __restrict__ xr, const float* __restrict__ xi,
                               int xbound) {
    __shared__ ulonglong2 shX[R1 * DIN];     // 16 KB dup-packed
    int tid = threadIdx.x;
    int j = tid & (H - 1);
    int g = tid >> 7;                        // rows g*8 .. g*8+7
    int row0 = blockIdx.x * R1;

    for (int i = tid; i < R1 * DIN; i += 256) {
        int m = i >> 6, d = i & 63;
        int src = iclamp((row0 + m) * DIN + d, xbound);
        shX[i] = make_ulonglong2(dup2(xr[src]), dup2(xi[src]));
    }
    __syncthreads();

    unsigned long long accA[8], accB[8];
#pragma unroll
    for (int m = 0; m < 8; m++) { accA[m] = 0ULL; accB[m] = 0ULL; }
#pragma unroll 2
    for (int d = 0; d < DIN; d++) {
        unsigned long long w = *(const unsigned long long*)(g_WI2 + d * H + j);
#pragma unroll
        for (int m = 0; m < 8; m++) {
            ulonglong2 hv = shX[(g * 8 + m) * DIN + d];
            accA[m] = ffma2(hv.x, w, accA[m]);
            accB[m] = ffma2(hv.y, w, accB[m]);
        }
    }
#pragma unroll
    for (int m = 0; m < 8; m++) {
        int rr = row0 + g * 8 + m;
        g_xp[rr * H + j] = make_float2(lo2(accA[m]) - hi2(accB[m]),
                                       hi2(accA[m]) + lo2(accB[m]));
    }
}

// ---------------- K2: complex matrix squaring (for M^CHUNK) ----------------
__global__ void matsq_kernel(int mode) {
    const float2* A = (mode == 0) ? g_M : ((mode & 1) ? g_P0 : g_P1);
    float2* Cd = (mode & 1) ? g_P1 : g_P0;
    __shared__ float2 arow[H];
    int k = blockIdx.x, j = threadIdx.x;
    arow[j] = A[k * H + j];
    __syncthreads();
    float re = 0.f, im = 0.f;
#pragma unroll 4
    for (int p = 0; p < H; p++) {
        float2 a = arow[p];
        float2 bb = A[p * H + j];
        re = fmaf(a.x, bb.x, re);
        re = fmaf(-a.y, bb.y, re);
        im = fmaf(a.x, bb.y, im);
        im = fmaf(a.y, bb.x, im);
    }
    Cd[k * H + j] = make_float2(re, im);
}

// ---------------- K3: phase A — local recurrence, 4 rows/CTA, xp from global ----------------
// grid 256 = (chunk c = blk>>2) x (batch quarter = blk&3), 256 threads = (j, g)
__global__ void phaseA_kernel() {
    __shared__ ulonglong2 shH[4 * H];        // 8 KB dup-packed
    int tid = threadIdx.x;
    int j = tid & (H - 1);
    int g = tid >> 7;                        // rows g*2 .. g*2+1
    int c = blockIdx.x >> 2;
    int bbase = (blockIdx.x & 3) * 4;

    for (int i = tid; i < 4 * H; i += 256) shH[i] = make_ulonglong2(0ULL, 0ULL);

    int t0 = c * CHUNK;
    float2 pre[2];
#pragma unroll
    for (int m = 0; m < 2; m++)
        pre[m] = g_xp[((bbase + g * 2 + m) * T + t0) * H + j];
    __syncthreads();

    float rRe[2], rIm[2];
    for (int js = 0; js < CHUNK; js++) {
        unsigned long long accA[2] = {0, 0}, accB[2] = {0, 0};
#pragma unroll 4
        for (int k = 0; k < H; k++) {
            unsigned long long w = *(const unsigned long long*)(g_M + k * H + j);
#pragma unroll
            for (int m = 0; m < 2; m++) {
                ulonglong2 hv = shH[(g * 2 + m) * H + k];
                accA[m] = ffma2(hv.x, w, accA[m]);
                accB[m] = ffma2(hv.y, w, accB[m]);
            }
        }
        float2 xv0 = pre[0], xv1 = pre[1];
        if (js + 1 < CHUNK) {
            int t1 = t0 + js + 1;
#pragma unroll
            for (int m = 0; m < 2; m++)
                pre[m] = g_xp[((bbase + g * 2 + m) * T + t1) * H + j];
        }
        __syncthreads();
        rRe[0] = xv0.x + lo2(accA[0]) - hi2(accB[0]);
        rIm[0] = xv0.y + hi2(accA[0]) + lo2(accB[0]);
        rRe[1] = xv1.x + lo2(accA[1]) - hi2(accB[1]);
        rIm[1] = xv1.y + hi2(accA[1]) + lo2(accB[1]);
        shH[(g * 2 + 0) * H + j] = make_ulonglong2(dup2(rRe[0]), dup2(rIm[0]));
        shH[(g * 2 + 1) * H + j] = make_ulonglong2(dup2(rRe[1]), dup2(rIm[1]));
        __syncthreads();
    }
#pragma unroll
    for (int m = 0; m < 2; m++)
        g_L[(c * B + bbase + g * 2 + m) * H + j] = make_float2(rRe[m], rIm[m]);
}

// ---------------- K4: phase 2 — boundary scan S_c = L_c + S_{c-1} * M^64 ----------------
__global__ void phase2_kernel() {
    __shared__ float2 shS[H];
    int h = threadIdx.x;       // 128 threads
    int b = blockIdx.x;        // 16 blocks
    float2 s = g_L[b * H + h];
    g_S[b * H + h] = s;
    shS[h] = s;
    __syncthreads();
    for (int c = 1; c < NC; c++) {
        float re = 0.f, im = 0.f;
#pragma unroll 4
        for (int k = 0; k < H; k++) {
            float2 w = g_P1[k * H + h];
            float2 hv = shS[k];
            re = fmaf(hv.x, w.x, re);
            re = fmaf(-hv.y, w.y, re);
            im = fmaf(hv.x, w.y, im);
            im = fmaf(hv.y, w.x, im);
        }
        __syncthreads();
        float2 l = g_L[(c * B + b) * H + h];
        s = make_float2(l.x + re, l.y + im);
        g_S[(c * B + b) * H + h] = s;
        shS[h] = s;
        __syncthreads();
    }
}

// ---------------- K5: phase B — exact-init replay + fused out-proj, 4 rows/CTA ----------------
// Output layout adaptive (FROZEN logic from passing R9 kernel).
__global__ void phaseB_kernel(float* __restrict__ outf, int fcap, int interleave) {
    __shared__ ulonglong2 shH[4 * H];        // 8 KB
    __shared__ float2 shP[4 * H];            // 4 KB partials
    int tid = threadIdx.x;
    int j = tid & (H - 1);
    int g = tid >> 7;
    int c = blockIdx.x >> 2;
    int bbase = (blockIdx.x & 3) * 4;
    int o = j & (DOUT - 1);
    int half = j >> 6;
    int r_cmb = tid >> 6;                    // 0..3: row for the combine step
    int o_cmb = tid & (DOUT - 1);

    for (int i = tid; i < 4 * H; i += 256) {
        int row = i >> 7, k = i & (H - 1);
        float2 s = (c == 0) ? make_float2(0.f, 0.f)
                            : g_S[((c - 1) * B + bbase + row) * H + k];
        shH[i] = make_ulonglong2(dup2(s.x), dup2(s.y));
    }

    int t0 = c * CHUNK;
    float2 pre[2];
#pragma unroll
    for (int m = 0; m < 2; m++)
        pre[m] = g_xp[((bbase + g * 2 + m) * T + t0) * H + j];
    __syncthreads();

    for (int js = 0; js < CHUNK; js++) {
        int t = t0 + js;
        unsigned long long accA[2] = {0, 0}, accB[2] = {0, 0};
#pragma unroll 4
        for (int k = 0; k < H; k++) {
            unsigned long long w = *(const unsigned long long*)(g_M + k * H + j);
#pragma unroll
            for (int m = 0; m < 2; m++) {
                ulonglong2 hv = shH[(g * 2 + m) * H + k];
                accA[m] = ffma2(hv.x, w, accA[m]);
                accB[m] = ffma2(hv.y, w, accB[m]);
            }
        }
        float2 xv0 = pre[0], xv1 = pre[1];
        if (js + 1 < CHUNK) {
            int t1 = t + 1;
#pragma unroll
            for (int m = 0; m < 2; m++)
                pre[m] = g_xp[((bbase + g * 2 + m) * T + t1) * H + j];
        }
        __syncthreads();
        {
            float re0 = xv0.x + lo2(accA[0]) - hi2(accB[0]);
            float im0 = xv0.y + hi2(accA[0]) + lo2(accB[0]);
            float re1 = xv1.x + lo2(accA[1]) - hi2(accB[1]);
            float im1 = xv1.y + hi2(accA[1]) + lo2(accB[1]);
            shH[(g * 2 + 0) * H + j] = make_ulonglong2(dup2(re0), dup2(im0));
            shH[(g * 2 + 1) * H + j] = make_ulonglong2(dup2(re1), dup2(im1));
        }
        __syncthreads();
        // fused out-proj partials over this thread's 64-k half (packed)
        unsigned long long pA[2] = {0, 0}, pB[2] = {0, 0};
#pragma unroll 4
        for (int kk = 0; kk < 64; kk++) {
            int k = half * 64 + kk;
            unsigned long long w = *(const unsigned long long*)(g_WO2 + k * DOUT + o);
#pragma unroll
            for (int m = 0; m < 2; m++) {
                ulonglong2 hv = shH[(g * 2 + m) * H + k];
                pA[m] = ffma2(hv.x, w, pA[m]);
                pB[m] = ffma2(hv.y, w, pB[m]);
            }
        }
#pragma unroll
        for (int m = 0; m < 2; m++)
            shP[(g * 2 + m) * H + half * 64 + o] =
                make_float2(lo2(pA[m]) - hi2(pB[m]), hi2(pA[m]) + lo2(pB[m]));
        __syncthreads();
        // combine halves + store (FROZEN output logic)
        {
            float2 p0 = shP[r_cmb * H + o_cmb];
            float2 p1 = shP[r_cmb * H + 64 + o_cmb];
            float re = p0.x + p1.x;
            float im = p0.y + p1.y;
            int oi = ((bbase + r_cmb) * T + t) * DOUT + o_cmb;   // 0 .. OUTP-1
            if (interleave) {
                int f0 = 2 * oi;
                if (f0 + 1 < fcap) { outf[f0] = re; outf[f0 + 1] = im; }
            } else {
                if (oi < fcap) outf[oi] = re;                    // real part only
            }
        }
        __syncthreads();
    }
}

// ---------------- launch ----------------
static inline int ebound(int reported, int expected) {
    if (reported >= 1 && reported < expected) return reported;
    return expected;
}
static inline int gidx(int i, int n_in) { return (i >= 0 && i < n_in) ? i : 0; }

extern "C" void kernel_launch(void* const* d_in, const int* in_sizes, int n_in,
                              void* d_out, int out_size) {
    int ix[2] = {0, 1}, iwh[2] = {4, 5}, iw8[4] = {2, 3, 6, 7};
    int nx = 0, nwh = 0, n8 = 0;
    for (int i = 0; i < n_in; i++) {
        int s = in_sizes[i];
        if (s == XN)        { if (nx  < 2) ix[nx++]  = i; }
        else if (s == WHN)  { if (nwh < 2) iwh[nwh++] = i; }
        else if (s == WIN)  { if (n8  < 4) iw8[n8++]  = i; }
    }
    const float* xr  = (const float*)d_in[gidx(ix[0],  n_in)];
    const float* xi  = (const float*)d_in[gidx(ix[1],  n_in)];
    const float* Wir = (const float*)d_in[gidx(iw8[0], n_in)];
    const float* Wii = (const float*)d_in[gidx(iw8[1], n_in)];
    const float* Wor = (const float*)d_in[gidx(iw8[2], n_in)];
    const float* Woi = (const float*)d_in[gidx(iw8[3], n_in)];
    const float* Whr = (const float*)d_in[gidx(iwh[0], n_in)];
    const float* Whi = (const float*)d_in[gidx(iwh[1], n_in)];

    int bx  = ebound(in_sizes[gidx(ix[0],  n_in)], XN);
    int b2  = ebound(in_sizes[gidx(ix[1],  n_in)], XN);   if (b2 < bx)  bx  = b2;
    int bwi = ebound(in_sizes[gidx(iw8[0], n_in)], WIN);
    b2      = ebound(in_sizes[gidx(iw8[1], n_in)], WIN);  if (b2 < bwi) bwi = b2;
    int bwo = ebound(in_sizes[gidx(iw8[2], n_in)], WIN);
    b2      = ebound(in_sizes[gidx(iw8[3], n_in)], WIN);  if (b2 < bwo) bwo = b2;
    int bwh = ebound(in_sizes[gidx(iwh[0], n_in)], WHN);
    b2      = ebound(in_sizes[gidx(iwh[1], n_in)], WHN);  if (b2 < bwh) bwh = b2;

    // FROZEN output-capacity logic (from passing R9 kernel)
    int fcap = out_size;
    if (fcap < 1) fcap = 1;
    if (fcap > 2 * OUTP) fcap = 2 * OUTP;
    int interleave = (fcap > OUTP) ? 1 : 0;

    // Launch order arranged so the 6th launch is phaseA (ncu -s 5 -c 1 profiles it).
    prep_kernel<<<(H * H + 255) / 256, 256>>>(Wir, Wii, bwi,
                                              Whr, Whi, bwh,
                                              Wor, Woi, bwo);          // 1
    proj_in_kernel<<<(B * T) / R1, 256>>>(xr, xi, bx);                 // 2
    matsq_kernel<<<H, H>>>(0);                                         // 3
    matsq_kernel<<<H, H>>>(1);                                         // 4
    matsq_kernel<<<H, H>>>(2);                                         // 5
    phaseA_kernel<<<NC * 4, 256>>>();                                  // 6  <- profiled
    matsq_kernel<<<H, H>>>(3);                                         // 7
    matsq_kernel<<<H, H>>>(4);                                         // 8
    matsq_kernel<<<H, H>>>(5);                                         // 9
    phase2_kernel<<<B, H>>>();                                         // 10
    phaseB_kernel<<<NC * 4, 256>>>((float*)d_out, fcap, interleave);   // 11
}

// round 11
// speedup vs baseline: 2.6407x; 1.3604x over previous
#include <cuda_runtime.h>

#define B    16
#define T    4096
#define DIN  64
#define DOUT 64
#define H    128
#define NC   64          // number of chunks
#define CHUNK 64         // T / NC

#define XN   (B * T * DIN)           // 4194304 elements per x buffer
#define WHN  (H * H)                 // 16384
#define WIN  (H * DIN)               // 8192
#define OUTP (B * T * DOUT)          // 4194304 output positions (complex)

// ---------------- scratch ----------------
__device__ float2 g_xp[B * T * H];   // input projection, 64 MB
__device__ float2 g_M[H * H];        // M[k][j] = i * Wh[j][k]
__device__ float2 g_P0[H * H];       // ping-pong for repeated squaring
__device__ float2 g_P1[H * H];       // ends as M^CHUNK
__device__ float2 g_WI2[DIN * H];    // Wi packed (re,im), d-major
__device__ float2 g_WO2[H * DOUT];   // Wo packed (re,im), k-major
__device__ float2 g_L[NC * B * H];   // chunk-local end states
__device__ float2 g_S[NC * B * H];   // scanned chunk-end states

__device__ __forceinline__ int iclamp(int i, int bound) {
    return (i < bound) ? ((i >= 0) ? i : 0) : (bound - 1);
}

// ---------------- packed f32x2 helpers ----------------
__device__ __forceinline__ unsigned long long ffma2(unsigned long long a,
                                                    unsigned long long b,
                                                    unsigned long long c) {
    unsigned long long d;
    asm("fma.rn.f32x2 %0, %1, %2, %3;" : "=l"(d) : "l"(a), "l"(b), "l"(c));
    return d;
}
__device__ __forceinline__ unsigned long long dup2(float x) {
    unsigned int u = __float_as_uint(x);
    return ((unsigned long long)u << 32) | (unsigned long long)u;
}
__device__ __forceinline__ float lo2(unsigned long long v) {
    return __uint_as_float((unsigned int)v);
}
__device__ __forceinline__ float hi2(unsigned long long v) {
    return __uint_as_float((unsigned int)(v >> 32));
}

// ---------------- K0: build M, packed Wi, packed Wo (reads clamped) ----------------
__global__ void prep_kernel(const float* __restrict__ Wir, const float* __restrict__ Wii, int bWi,
                            const float* __restrict__ Whr, const float* __restrict__ Whi, int bWh,
                            const float* __restrict__ Wor, const float* __restrict__ Woi, int bWo) {
    int idx = blockIdx.x * blockDim.x + threadIdx.x;
    if (idx < H * H) {
        int k = idx / H, j = idx - k * H;
        int s = iclamp(j * H + k, bWh);
        g_M[idx] = make_float2(-Whi[s], Whr[s]);
    }
    if (idx < DIN * H) {
        int d = idx / H, j = idx - d * H;
        int s = iclamp(j * DIN + d, bWi);
        g_WI2[idx] = make_float2(Wir[s], Wii[s]);
    }
    if (idx < H * DOUT) {
        int k = idx / DOUT, o = idx - k * DOUT;
        int s = iclamp(o * H + k, bWo);
        g_WO2[idx] = make_float2(Wor[s], Woi[s]);
    }
}

// ---------------- K1: input projection xp = x @ Wi^T (f32x2), once ----------------
#define R1 16
__global__ void proj_in_kernel(const float* __restrict__ xr, const float* __restrict__ xi,
                               int xbound) {
    __shared__ ulonglong2 shX[R1 * DIN];     // 16 KB dup-packed
    int tid = threadIdx.x;
    int j = tid & (H - 1);
    int g = tid >> 7;                        // rows g*8 .. g*8+7
    int row0 = blockIdx.x * R1;

    for (int i = tid; i < R1 * DIN; i += 256) {
        int m = i >> 6, d = i & 63;
        int src = iclamp((row0 + m) * DIN + d, xbound);
        shX[i] = make_ulonglong2(dup2(xr[src]), dup2(xi[src]));
    }
    __syncthreads();

    unsigned long long accA[8], accB[8];
#pragma unroll
    for (int m = 0; m < 8; m++) { accA[m] = 0ULL; accB[m] = 0ULL; }
#pragma unroll 2
    for (int d = 0; d < DIN; d++) {
        unsigned long long w = *(const unsigned long long*)(g_WI2 + d * H + j);
#pragma unroll
        for (int m = 0; m < 8; m++) {
            ulonglong2 hv = shX[(g * 8 + m) * DIN + d];
            accA[m] = ffma2(hv.x, w, accA[m]);
            accB[m] = ffma2(hv.y, w, accB[m]);
        }
    }
#pragma unroll
    for (int m = 0; m < 8; m++) {
        int rr = row0 + g * 8 + m;
        g_xp[rr * H + j] = make_float2(lo2(accA[m]) - hi2(accB[m]),
                                       hi2(accA[m]) + lo2(accB[m]));
    }
}

// ---------------- K2: complex matrix squaring (for M^CHUNK) ----------------
__global__ void matsq_kernel(int mode) {
    const float2* A = (mode == 0) ? g_M : ((mode & 1) ? g_P0 : g_P1);
    float2* Cd = (mode & 1) ? g_P1 : g_P0;
    __shared__ float2 arow[H];
    int k = blockIdx.x, j = threadIdx.x;
    arow[j] = A[k * H + j];
    __syncthreads();
    float re = 0.f, im = 0.f;
#pragma unroll 4
    for (int p = 0; p < H; p++) {
        float2 a = arow[p];
        float2 bb = A[p * H + j];
        re = fmaf(a.x, bb.x, re);
        re = fmaf(-a.y, bb.y, re);
        im = fmaf(a.x, bb.y, im);
        im = fmaf(a.y, bb.x, im);
    }
    Cd[k * H + j] = make_float2(re, im);
}

// ---------------- K3: phase A — local recurrence, register-resident M ----------------
// grid 256 = (chunk c = blk>>2) x (batch quarter = blk&3), 256 threads = (j, kh)
// Thread preloads M[kh*64..kh*64+63][j] into 64 regs pairs; zero weight loads in t-loop.
__global__ void __launch_bounds__(256, 1) phaseA_kernel() {
    __shared__ ulonglong2 shH[4 * H];        // 8 KB dup-packed h state
    __shared__ float2 shP[8 * H];            // 8 KB half-partials [row*2+kh][j]
    int tid = threadIdx.x;
    int j = tid & (H - 1);
    int kh = tid >> 7;                       // k-half 0/1
    int c = blockIdx.x >> 2;
    int bbase = (blockIdx.x & 3) * 4;
    int kbase = kh * 64;

    unsigned long long wk[64];
#pragma unroll
    for (int kk = 0; kk < 64; kk++)
        wk[kk] = *(const unsigned long long*)(g_M + (kbase + kk) * H + j);

    for (int i = tid; i < 4 * H; i += 256) shH[i] = make_ulonglong2(0ULL, 0ULL);

    int t0 = c * CHUNK;
    float2 pre[2];
#pragma unroll
    for (int m = 0; m < 2; m++)
        pre[m] = g_xp[((bbase + kh * 2 + m) * T + t0) * H + j];
    __syncthreads();

    float2 hlast[2];
    for (int js = 0; js < CHUNK; js++) {
        unsigned long long accA[4] = {0, 0, 0, 0}, accB[4] = {0, 0, 0, 0};
#pragma unroll
        for (int kk = 0; kk < 64; kk++) {
            unsigned long long w = wk[kk];
#pragma unroll
            for (int row = 0; row < 4; row++) {
                ulonglong2 hv = shH[row * H + kbase + kk];
                accA[row] = ffma2(hv.x, w, accA[row]);
                accB[row] = ffma2(hv.y, w, accB[row]);
            }
        }
#pragma unroll
        for (int row = 0; row < 4; row++)
            shP[(row * 2 + kh) * H + j] =
                make_float2(lo2(accA[row]) - hi2(accB[row]),
                            hi2(accA[row]) + lo2(accB[row]));
        __syncthreads();
        // combine halves for this thread's 2 rows, add xp, update state
#pragma unroll
        for (int m = 0; m < 2; m++) {
            int row = kh * 2 + m;
            float2 p0 = shP[(row * 2 + 0) * H + j];
            float2 p1 = shP[(row * 2 + 1) * H + j];
            float re = pre[m].x + p0.x + p1.x;
            float im = pre[m].y + p0.y + p1.y;
            hlast[m] = make_float2(re, im);
            shH[row * H + j] = make_ulonglong2(dup2(re), dup2(im));
        }
        if (js + 1 < CHUNK) {
            int t1 = t0 + js + 1;
#pragma unroll
            for (int m = 0; m < 2; m++)
                pre[m] = g_xp[((bbase + kh * 2 + m) * T + t1) * H + j];
        }
        __syncthreads();
    }
#pragma unroll
    for (int m = 0; m < 2; m++)
        g_L[(c * B + bbase + kh * 2 + m) * H + j] = hlast[m];
}

// ---------------- K4: phase 2 — boundary scan S_c = L_c + S_{c-1} * M^64 ----------------
__global__ void phase2_kernel() {
    __shared__ float2 shS[H];
    int h = threadIdx.x;       // 128 threads
    int b = blockIdx.x;        // 16 blocks
    float2 s = g_L[b * H + h];
    g_S[b * H + h] = s;
    shS[h] = s;
    __syncthreads();
    for (int c = 1; c < NC; c++) {
        float re = 0.f, im = 0.f;
#pragma unroll 4
        for (int k = 0; k < H; k++) {
            float2 w = g_P1[k * H + h];
            float2 hv = shS[k];
            re = fmaf(hv.x, w.x, re);
            re = fmaf(-hv.y, w.y, re);
            im = fmaf(hv.x, w.y, im);
            im = fmaf(hv.y, w.x, im);
        }
        __syncthreads();
        float2 l = g_L[(c * B + b) * H + h];
        s = make_float2(l.x + re, l.y + im);
        g_S[(c * B + b) * H + h] = s;
        shS[h] = s;
        __syncthreads();
    }
}

// ---------------- K5: phase B — register-M replay + fused out-proj ----------------
// Output layout adaptive (FROZEN logic from passing kernels).
__global__ void __launch_bounds__(256, 1) phaseB_kernel(float* __restrict__ outf,
                                                        int fcap, int interleave) {
    __shared__ ulonglong2 shH[4 * H];        // 8 KB
    __shared__ float2 shP[8 * H];            // 8 KB half-partials (recurrence)
    __shared__ float2 shPo[8 * DOUT];        // 4 KB out-proj partials [row*2+oh][o]
    int tid = threadIdx.x;
    int j = tid & (H - 1);
    int kh = tid >> 7;
    int c = blockIdx.x >> 2;
    int bbase = (blockIdx.x & 3) * 4;
    int kbase = kh * 64;
    int o = j & (DOUT - 1);
    int oh = j >> 6;                         // out-proj k-half
    int r_cmb = tid >> 6;                    // 0..3 combine row
    int o_cmb = tid & (DOUT - 1);

    unsigned long long wk[64];
#pragma unroll
    for (int kk = 0; kk < 64; kk++)
        wk[kk] = *(const unsigned long long*)(g_M + (kbase + kk) * H + j);

    for (int i = tid; i < 4 * H; i += 256) {
        int row = i >> 7, k = i & (H - 1);
        float2 s = (c == 0) ? make_float2(0.f, 0.f)
                            : g_S[((c - 1) * B + bbase + row) * H + k];
        shH[i] = make_ulonglong2(dup2(s.x), dup2(s.y));
    }

    int t0 = c * CHUNK;
    float2 pre[2];
#pragma unroll
    for (int m = 0; m < 2; m++)
        pre[m] = g_xp[((bbase + kh * 2 + m) * T + t0) * H + j];
    __syncthreads();

    for (int js = 0; js < CHUNK; js++) {
        int t = t0 + js;
        unsigned long long accA[4] = {0, 0, 0, 0}, accB[4] = {0, 0, 0, 0};
#pragma unroll
        for (int kk = 0; kk < 64; kk++) {
            unsigned long long w = wk[kk];
#pragma unroll
            for (int row = 0; row < 4; row++) {
                ulonglong2 hv = shH[row * H + kbase + kk];
                accA[row] = ffma2(hv.x, w, accA[row]);
                accB[row] = ffma2(hv.y, w, accB[row]);
            }
        }
#pragma unroll
        for (int row = 0; row < 4; row++)
            shP[(row * 2 + kh) * H + j] =
                make_float2(lo2(accA[row]) - hi2(accB[row]),
                            hi2(accA[row]) + lo2(accB[row]));
        __syncthreads();
#pragma unroll
        for (int m = 0; m < 2; m++) {
            int row = kh * 2 + m;
            float2 p0 = shP[(row * 2 + 0) * H + j];
            float2 p1 = shP[(row * 2 + 1) * H + j];
            float re = pre[m].x + p0.x + p1.x;
            float im = pre[m].y + p0.y + p1.y;
            shH[row * H + j] = make_ulonglong2(dup2(re), dup2(im));
        }
        if (js + 1 < CHUNK) {
            int t1 = t + 1;
#pragma unroll
            for (int m = 0; m < 2; m++)
                pre[m] = g_xp[((bbase + kh * 2 + m) * T + t1) * H + j];
        }
        __syncthreads();
        // fused out-proj: thread (o, oh) x 2 rows (kh-selected) over 64-k half
        unsigned long long pA[2] = {0, 0}, pB[2] = {0, 0};
#pragma unroll 4
        for (int kk = 0; kk < 64; kk++) {
            int k = oh * 64 + kk;
            unsigned long long w = *(const unsigned long long*)(g_WO2 + k * DOUT + o);
#pragma unroll
            for (int m = 0; m < 2; m++) {
                ulonglong2 hv = shH[(kh * 2 + m) * H + k];
                pA[m] = ffma2(hv.x, w, pA[m]);
                pB[m] = ffma2(hv.y, w, pB[m]);
            }
        }
#pragma unroll
        for (int m = 0; m < 2; m++)
            shPo[((kh * 2 + m) * 2 + oh) * DOUT + o] =
                make_float2(lo2(pA[m]) - hi2(pB[m]), hi2(pA[m]) + lo2(pB[m]));
        __syncthreads();
        // combine halves + store (FROZEN output logic)
        {
            float2 p0 = shPo[(r_cmb * 2 + 0) * DOUT + o_cmb];
            float2 p1 = shPo[(r_cmb * 2 + 1) * DOUT + o_cmb];
            float re = p0.x + p1.x;
            float im = p0.y + p1.y;
            int oi = ((bbase + r_cmb) * T + t) * DOUT + o_cmb;   // 0 .. OUTP-1
            if (interleave) {
                int f0 = 2 * oi;
                if (f0 + 1 < fcap) { outf[f0] = re; outf[f0 + 1] = im; }
            } else {
                if (oi < fcap) outf[oi] = re;                    // real part only
            }
        }
        __syncthreads();
    }
}

// ---------------- launch ----------------
static inline int ebound(int reported, int expected) {
    if (reported >= 1 && reported < expected) return reported;
    return expected;
}
static inline int gidx(int i, int n_in) { return (i >= 0 && i < n_in) ? i : 0; }

extern "C" void kernel_launch(void* const* d_in, const int* in_sizes, int n_in,
                              void* d_out, int out_size) {
    int ix[2] = {0, 1}, iwh[2] = {4, 5}, iw8[4] = {2, 3, 6, 7};
    int nx = 0, nwh = 0, n8 = 0;
    for (int i = 0; i < n_in; i++) {
        int s = in_sizes[i];
        if (s == XN)        { if (nx  < 2) ix[nx++]  = i; }
        else if (s == WHN)  { if (nwh < 2) iwh[nwh++] = i; }
        else if (s == WIN)  { if (n8  < 4) iw8[n8++]  = i; }
    }
    const float* xr  = (const float*)d_in[gidx(ix[0],  n_in)];
    const float* xi  = (const float*)d_in[gidx(ix[1],  n_in)];
    const float* Wir = (const float*)d_in[gidx(iw8[0], n_in)];
    const float* Wii = (const float*)d_in[gidx(iw8[1], n_in)];
    const float* Wor = (const float*)d_in[gidx(iw8[2], n_in)];
    const float* Woi = (const float*)d_in[gidx(iw8[3], n_in)];
    const float* Whr = (const float*)d_in[gidx(iwh[0], n_in)];
    const float* Whi = (const float*)d_in[gidx(iwh[1], n_in)];

    int bx  = ebound(in_sizes[gidx(ix[0],  n_in)], XN);
    int b2  = ebound(in_sizes[gidx(ix[1],  n_in)], XN);   if (b2 < bx)  bx  = b2;
    int bwi = ebound(in_sizes[gidx(iw8[0], n_in)], WIN);
    b2      = ebound(in_sizes[gidx(iw8[1], n_in)], WIN);  if (b2 < bwi) bwi = b2;
    int bwo = ebound(in_sizes[gidx(iw8[2], n_in)], WIN);
    b2      = ebound(in_sizes[gidx(iw8[3], n_in)], WIN);  if (b2 < bwo) bwo = b2;
    int bwh = ebound(in_sizes[gidx(iwh[0], n_in)], WHN);
    b2      = ebound(in_sizes[gidx(iwh[1], n_in)], WHN);  if (b2 < bwh) bwh = b2;

    // FROZEN output-capacity logic
    int fcap = out_size;
    if (fcap < 1) fcap = 1;
    if (fcap > 2 * OUTP) fcap = 2 * OUTP;
    int interleave = (fcap > OUTP) ? 1 : 0;

    // Harness issues 1 kernel before ours; ncu -s 5 profiles overall #6 = our #5.
    prep_kernel<<<(H * H + 255) / 256, 256>>>(Wir, Wii, bwi,
                                              Whr, Whi, bwh,
                                              Wor, Woi, bwo);          // ours 1
    proj_in_kernel<<<(B * T) / R1, 256>>>(xr, xi, bx);                 // ours 2
    matsq_kernel<<<H, H>>>(0);                                         // ours 3
    matsq_kernel<<<H, H>>>(1);                                         // ours 4
    phaseA_kernel<<<NC * 4, 256>>>();                                  // ours 5 <- profiled
    matsq_kernel<<<H, H>>>(2);                                         // ours 6
    matsq_kernel<<<H, H>>>(3);                                         // ours 7
    matsq_kernel<<<H, H>>>(4);                                         // ours 8
    matsq_kernel<<<H, H>>>(5);                                         // ours 9
    phase2_kernel<<<B, H>>>();                                         // ours 10
    phaseB_kernel<<<NC * 4, 256>>>((float*)d_out, fcap, interleave);   // ours 11
}